// round 1
// baseline (speedup 1.0000x reference)
#include <cuda_runtime.h>

#define N_ROWS 1024
#define T_LEN  2048
#define E_NUM  16384
#define K_TAPS 32

// Scratch (no allocations allowed): expert permutation grouped by dst + bucket offsets.
__device__ int g_perm[E_NUM];
__device__ int g_off[N_ROWS + 1];

// ---------------------------------------------------------------------------
// Phase 1: counting-sort experts by dst. Single block of 1024 threads.
// ---------------------------------------------------------------------------
__global__ void bucket_kernel(const int* __restrict__ dst) {
    __shared__ int cnt[N_ROWS];
    __shared__ int scan[N_ROWS];
    int tid = threadIdx.x;

    cnt[tid] = 0;
    __syncthreads();
    for (int e = tid; e < E_NUM; e += N_ROWS) atomicAdd(&cnt[dst[e]], 1);
    __syncthreads();

    // Hillis-Steele inclusive scan -> exclusive
    int v = cnt[tid];
    scan[tid] = v;
    __syncthreads();
    for (int ofs = 1; ofs < N_ROWS; ofs <<= 1) {
        int add = (tid >= ofs) ? scan[tid - ofs] : 0;
        __syncthreads();
        scan[tid] += add;
        __syncthreads();
    }
    int excl = scan[tid] - v;
    g_off[tid] = excl;
    if (tid == N_ROWS - 1) g_off[N_ROWS] = E_NUM;
    cnt[tid] = excl;            // reuse as scatter cursor
    __syncthreads();

    for (int e = tid; e < E_NUM; e += N_ROWS) {
        int pos = atomicAdd(&cnt[dst[e]], 1);
        g_perm[pos] = e;
    }
}

// ---------------------------------------------------------------------------
// Phase 1b: sort each bucket (determinism; buckets are ~16 elements).
// ---------------------------------------------------------------------------
__global__ void sort_kernel() {
    int n = blockIdx.x * blockDim.x + threadIdx.x;
    if (n >= N_ROWS) return;
    int b = g_off[n], e = g_off[n + 1];
    for (int i = b + 1; i < e; ++i) {
        int key = g_perm[i];
        int j = i - 1;
        while (j >= b && g_perm[j] > key) { g_perm[j + 1] = g_perm[j]; --j; }
        g_perm[j + 1] = key;
    }
}

// ---------------------------------------------------------------------------
// Phase 2: one block per dst row. Stage src row in smem (32-float zero halo),
// sliding-window registers, accumulate all experts, write once (no atomics).
// ---------------------------------------------------------------------------
__global__ __launch_bounds__(256)
void conv_route_kernel(const float* __restrict__ x,
                       const float* __restrict__ w,
                       const int*   __restrict__ src,
                       float*       __restrict__ out) {
    __shared__ float xs[K_TAPS + T_LEN];   // xs[32+t] = row[t]; xs[0..31] = 0
    __shared__ float wsh[K_TAPS];

    const int tid = threadIdx.x;
    const int n   = blockIdx.x;
    const int beg = g_off[n];
    const int end = g_off[n + 1];

    if (tid < K_TAPS) xs[tid] = 0.0f;      // causal halo, never overwritten

    float acc[8];
#pragma unroll
    for (int j = 0; j < 8; ++j) acc[j] = 0.0f;

    // Register double-buffer: prefetch first expert's row + weights.
    float4 s0 = make_float4(0.f, 0.f, 0.f, 0.f);
    float4 s1 = make_float4(0.f, 0.f, 0.f, 0.f);
    float  wreg = 0.0f;
    if (beg < end) {
        int e = g_perm[beg];
        const float4* row = (const float4*)(x + (size_t)src[e] * T_LEN);
        s0 = row[tid];
        s1 = row[tid + 256];
        if (tid < K_TAPS) wreg = w[e * K_TAPS + tid];
    }

    for (int i = beg; i < end; ++i) {
        __syncthreads();                               // prior compute done
        ((float4*)(xs + K_TAPS))[tid]       = s0;      // publish row i
        ((float4*)(xs + K_TAPS))[tid + 256] = s1;
        if (tid < K_TAPS) wsh[tid] = wreg;
        __syncthreads();

        if (i + 1 < end) {                             // prefetch row i+1
            int e = g_perm[i + 1];
            const float4* row = (const float4*)(x + (size_t)src[e] * T_LEN);
            s0 = row[tid];
            s1 = row[tid + 256];
            if (tid < K_TAPS) wreg = w[e * K_TAPS + tid];
        }

        // Sliding window: thread owns t0 = 8*tid .. t0+7, needs xs[8*tid .. 8*tid+39].
        float xv[40];
        const float4* xs4 = (const float4*)xs;
#pragma unroll
        for (int c = 0; c < 10; ++c) {
            float4 v = xs4[2 * tid + c];
            xv[4 * c + 0] = v.x; xv[4 * c + 1] = v.y;
            xv[4 * c + 2] = v.z; xv[4 * c + 3] = v.w;
        }

#pragma unroll
        for (int k = 0; k < K_TAPS; ++k) {
            float wk = wsh[k];
#pragma unroll
            for (int j = 0; j < 8; ++j)
                acc[j] += xv[32 + j - k] * wk;         // xv[m] = xs[8*tid+m]
        }
    }

    // Epilogue: out[n,t] = x[n,t] + acc
    const float4* xrow = (const float4*)(x + (size_t)n * T_LEN);
    float4 a = xrow[2 * tid], b = xrow[2 * tid + 1];
    a.x += acc[0]; a.y += acc[1]; a.z += acc[2]; a.w += acc[3];
    b.x += acc[4]; b.y += acc[5]; b.z += acc[6]; b.w += acc[7];
    float4* orow = (float4*)(out + (size_t)n * T_LEN);
    orow[2 * tid]     = a;
    orow[2 * tid + 1] = b;
}

// ---------------------------------------------------------------------------
extern "C" void kernel_launch(void* const* d_in, const int* in_sizes, int n_in,
                              void* d_out, int out_size) {
    const float* x   = (const float*)d_in[0];
    const float* w   = (const float*)d_in[1];
    const int*   src = (const int*)d_in[2];
    const int*   dst = (const int*)d_in[3];
    float*       out = (float*)d_out;

    bucket_kernel<<<1, N_ROWS>>>(dst);
    sort_kernel<<<4, 256>>>();
    conv_route_kernel<<<N_ROWS, 256>>>(x, w, src, out);
}